// round 1
// baseline (speedup 1.0000x reference)
#include <cuda_runtime.h>

#define IMG      512
#define TW       64
#define TH       32
#define HROWS    (TH + 10)          // 42
#define HSTRIDE  65                 // padded float4 row stride (bank-conflict mitigation)
#define NT       256
#define NPLANES  192                // 64 * 3
#define NPIX     (64.0 * 3.0 * 512.0 * 512.0)

// Gaussian taps, sigma=1.5, win=11, normalized (compile-time immediates)
__device__ constexpr float GW[11] = {
    1.0283886e-3f, 7.5988485e-3f, 3.6000773e-2f, 1.0936073e-1f, 2.1300553e-1f,
    2.6601180e-1f,
    2.1300553e-1f, 1.0936073e-1f, 3.6000773e-2f, 7.5988485e-3f, 1.0283886e-3f
};

#define C1F 4.0e-4f     // (0.01*2)^2
#define C2F 3.6e-3f     // (0.03*2)^2

__device__ double g_acc[2];   // [0]=sum (x-y)^2, [1]=sum ssim_map

__global__ void init_acc_kernel() {
    g_acc[0] = 0.0;
    g_acc[1] = 0.0;
}

__global__ void __launch_bounds__(NT) ssim_mse_kernel(
    const float* __restrict__ x, const float* __restrict__ y)
{
    // H[r][c] = horizontal 11-tap sums of {S=x+y, D=x-y, Q=x^2+y^2, P=x*y}
    __shared__ float4 H[HROWS][HSTRIDE];
    __shared__ float red_m[8], red_s[8];

    const int plane = blockIdx.z;
    const int row0  = blockIdx.y * TH;
    const int col0  = blockIdx.x * TW;
    const float* xp = x + (size_t)plane * (IMG * IMG);
    const float* yp = y + (size_t)plane * (IMG * IMG);
    const int tid = threadIdx.x;

    float mse_acc = 0.f;

    // ---------------- Phase A: horizontal pass ----------------
    // slot = r * 8 + g : row r of halo (0..41), col-group g (8 outputs each)
    for (int s = tid; s < HROWS * 8; s += NT) {
        const int r = s >> 3;
        const int g = s & 7;
        const int rimg  = row0 - 5 + r;
        const int cbase = col0 + g * 8 - 5;
        const bool rok = ((unsigned)rimg < IMG);
        const float* xr = xp + (size_t)rimg * IMG;
        const float* yr = yp + (size_t)rimg * IMG;
        const bool rowned = (r >= 5) && (r < 5 + TH);

        float sv[18], dv[18], qv[18], pv[18];
#pragma unroll
        for (int i = 0; i < 18; i++) {
            const int c = cbase + i;
            float xv = 0.f, yv = 0.f;
            if (rok && (unsigned)c < IMG) {
                xv = __ldg(xr + c);
                yv = __ldg(yr + c);
            }
            sv[i] = xv + yv;
            dv[i] = xv - yv;
            qv[i] = fmaf(xv, xv, yv * yv);
            pv[i] = xv * yv;
            // each interior point owned by exactly one (slot,i): i in [5,13), r in [5,5+TH)
            if (i >= 5 && i < 13) {
                if (rowned) mse_acc = fmaf(dv[i], dv[i], mse_acc);
            }
        }
#pragma unroll
        for (int j = 0; j < 8; j++) {
            float hs = 0.f, hd = 0.f, hq = 0.f, hp = 0.f;
#pragma unroll
            for (int k = 0; k < 11; k++) {
                hs = fmaf(GW[k], sv[j + k], hs);
                hd = fmaf(GW[k], dv[j + k], hd);
                hq = fmaf(GW[k], qv[j + k], hq);
                hp = fmaf(GW[k], pv[j + k], hp);
            }
            H[r][g * 8 + j] = make_float4(hs, hd, hq, hp);
        }
    }

    __syncthreads();

    // ---------------- Phase B: vertical pass + SSIM epilogue ----------------
    // 64 cols x 4 row-strips of 8 output rows each = 256 threads
    const int col   = tid & 63;
    const int strip = tid >> 6;
    const int rb    = strip * 8;

    float4 win[11];
#pragma unroll
    for (int k = 0; k < 10; k++) win[k] = H[rb + k][col];

    float ssim_acc = 0.f;
#pragma unroll
    for (int r = 0; r < 8; r++) {
        win[(r + 10) % 11] = H[rb + r + 10][col];
        float S = 0.f, D = 0.f, Q = 0.f, P = 0.f;
#pragma unroll
        for (int k = 0; k < 11; k++) {
            const float4 v = win[(r + k) % 11];
            S = fmaf(GW[k], v.x, S);
            D = fmaf(GW[k], v.y, D);
            Q = fmaf(GW[k], v.z, Q);
            P = fmaf(GW[k], v.w, P);
        }
        const float S2  = S * S;
        const float D2  = D * D;
        const float A   = 0.5f * (S2 - D2);   // 2*mu1*mu2
        const float Msq = 0.5f * (S2 + D2);   // mu1^2 + mu2^2
        const float num = (A + C1F) * (2.f * P - A + C2F);
        const float den = (Msq + C1F) * (Q - Msq + C2F);
        ssim_acc += __fdividef(num, den);
    }

    // ---------------- Reduction ----------------
#pragma unroll
    for (int o = 16; o > 0; o >>= 1) {
        mse_acc  += __shfl_down_sync(0xffffffffu, mse_acc,  o);
        ssim_acc += __shfl_down_sync(0xffffffffu, ssim_acc, o);
    }
    const int wid = tid >> 5;
    if ((tid & 31) == 0) { red_m[wid] = mse_acc; red_s[wid] = ssim_acc; }
    __syncthreads();
    if (tid < 32) {
        float m  = (tid < 8) ? red_m[tid] : 0.f;
        float ss = (tid < 8) ? red_s[tid] : 0.f;
#pragma unroll
        for (int o = 4; o > 0; o >>= 1) {
            m  += __shfl_down_sync(0xffffffffu, m,  o);
            ss += __shfl_down_sync(0xffffffffu, ss, o);
        }
        if (tid == 0) {
            atomicAdd(&g_acc[0], (double)m);
            atomicAdd(&g_acc[1], (double)ss);
        }
    }
}

__global__ void finalize_kernel(float* out) {
    const double mse  = g_acc[0] / NPIX;
    const double ssim = g_acc[1] / NPIX;
    out[0] = (float)(0.7 * mse + 0.3 * (1.0 - ssim));
}

extern "C" void kernel_launch(void* const* d_in, const int* in_sizes, int n_in,
                              void* d_out, int out_size)
{
    const float* recon = (const float*)d_in[0];
    const float* orig  = (const float*)d_in[1];
    float* out = (float*)d_out;

    init_acc_kernel<<<1, 1>>>();
    dim3 grid(IMG / TW, IMG / TH, NPLANES);   // 8 x 16 x 192
    ssim_mse_kernel<<<grid, NT>>>(recon, orig);
    finalize_kernel<<<1, 1>>>(out);
}

// round 2
// speedup vs baseline: 1.0517x; 1.0517x over previous
#include <cuda_runtime.h>

#define IMG      512
#define TW       64
#define TH       32
#define HROWS    (TH + 10)          // 42
#define HSTRIDE  65                 // padded float4 row stride
#define NT       256
#define NPLANES  192                // 64 * 3
#define NPIX     (64.0 * 3.0 * 512.0 * 512.0)

typedef unsigned long long u64;

// Gaussian taps, sigma=1.5, win=11, normalized
__device__ constexpr float GW[6] = {
    1.0283886e-3f, 7.5988485e-3f, 3.6000773e-2f, 1.0936073e-1f, 2.1300553e-1f,
    2.6601180e-1f
};

#define C1F 4.0e-4f     // (0.01*2)^2
#define C2F 3.6e-3f     // (0.03*2)^2

__device__ double g_acc[2];   // [0]=sum (x-y)^2, [1]=sum ssim_map

// ---------- packed f32x2 helpers (sm_103a FFMA2 path) ----------
__device__ __forceinline__ u64 pk2(float lo, float hi) {
    u64 r; asm("mov.b64 %0,{%1,%2};" : "=l"(r) : "f"(lo), "f"(hi)); return r;
}
__device__ __forceinline__ void upk(u64 a, float& lo, float& hi) {
    asm("mov.b64 {%0,%1},%2;" : "=f"(lo), "=f"(hi) : "l"(a));
}
__device__ __forceinline__ u64 f2fma(u64 a, u64 b, u64 c) {
    u64 d; asm("fma.rn.f32x2 %0,%1,%2,%3;" : "=l"(d) : "l"(a), "l"(b), "l"(c)); return d;
}
__device__ __forceinline__ u64 f2add(u64 a, u64 b) {
    u64 d; asm("add.rn.f32x2 %0,%1,%2;" : "=l"(d) : "l"(a), "l"(b)); return d;
}
__device__ __forceinline__ u64 f2mul(u64 a, u64 b) {
    u64 d; asm("mul.rn.f32x2 %0,%1,%2;" : "=l"(d) : "l"(a), "l"(b)); return d;
}

// 11-tap symmetric conv on packed pairs: 5 add2 + 1 mul2 + 5 fma2
__device__ __forceinline__ u64 conv11(const u64* w, const u64* G2) {
    u64 acc = f2mul(G2[5], w[5]);
#pragma unroll
    for (int k = 0; k < 5; k++)
        acc = f2fma(G2[k], f2add(w[k], w[10 - k]), acc);
    return acc;
}

__global__ void init_acc_kernel() { g_acc[0] = 0.0; g_acc[1] = 0.0; }

// ---------------- Phase A (templated on bounds checking) ----------------
template <bool SAFE>
__device__ __forceinline__ float phaseA(
    const float* __restrict__ xp, const float* __restrict__ yp,
    int row0, int col0, int tid, float4 (*H)[HSTRIDE], const u64* G2)
{
    float mse = 0.f;
    for (int s = tid; s < HROWS * 8; s += NT) {
        const int r = s >> 3;
        const int g = s & 7;
        const int rimg  = row0 - 5 + r;
        const int cbase = col0 + g * 8 - 5;
        const bool rok = SAFE ? ((unsigned)rimg < IMG) : true;
        const float* xr = xp + (size_t)rimg * IMG;
        const float* yr = yp + (size_t)rimg * IMG;

        float xv[18], yv[18];
#pragma unroll
        for (int i = 0; i < 18; i++) {
            float a = 0.f, b = 0.f;
            if (SAFE) {
                const int c = cbase + i;
                if (rok && (unsigned)c < IMG) { a = __ldg(xr + c); b = __ldg(yr + c); }
            } else {
                a = __ldg(xr + cbase + i); b = __ldg(yr + cbase + i);
            }
            xv[i] = a; yv[i] = b;
        }

        // MSE: interior ownership (r in [5,5+TH), i in [5,13))
        if (r >= 5 && r < 5 + TH) {
#pragma unroll
            for (int i = 5; i < 13; i++) {
                const float d = xv[i] - yv[i];
                mse = fmaf(d, d, mse);
            }
        }

        // --- SD stream pass ---
        u64 w[18];
#pragma unroll
        for (int i = 0; i < 18; i++) w[i] = pk2(xv[i] + yv[i], xv[i] - yv[i]);
        u64 out[8];
#pragma unroll
        for (int j = 0; j < 8; j++) out[j] = conv11(w + j, G2);
#pragma unroll
        for (int j = 0; j < 8; j++) {          // bank-rotated stores
            const int jj = (j + g) & 7;
            float a, b; upk(out[jj], a, b);
            reinterpret_cast<float2*>(&H[r][g * 8 + jj])[0] = make_float2(a, b);
        }

        // --- QP stream pass (reuse window regs; xv/yv die here) ---
#pragma unroll
        for (int i = 0; i < 18; i++)
            w[i] = pk2(fmaf(xv[i], xv[i], yv[i] * yv[i]), xv[i] * yv[i]);
#pragma unroll
        for (int j = 0; j < 8; j++) out[j] = conv11(w + j, G2);
#pragma unroll
        for (int j = 0; j < 8; j++) {
            const int jj = (j + g) & 7;
            float a, b; upk(out[jj], a, b);
            reinterpret_cast<float2*>(&H[r][g * 8 + jj])[1] = make_float2(a, b);
        }
    }
    return mse;
}

__global__ void __launch_bounds__(NT, 2) ssim_mse_kernel(
    const float* __restrict__ x, const float* __restrict__ y)
{
    __shared__ float4 H[HROWS][HSTRIDE];
    __shared__ float red_m[8], red_s[8];

    const int plane = blockIdx.z;
    const int row0  = blockIdx.y * TH;
    const int col0  = blockIdx.x * TW;
    const float* xp = x + (size_t)plane * (IMG * IMG);
    const float* yp = y + (size_t)plane * (IMG * IMG);
    const int tid = threadIdx.x;

    const u64 G2[6] = { pk2(GW[0], GW[0]), pk2(GW[1], GW[1]), pk2(GW[2], GW[2]),
                        pk2(GW[3], GW[3]), pk2(GW[4], GW[4]), pk2(GW[5], GW[5]) };

    const bool interior = (blockIdx.x >= 1) && (blockIdx.x <= 6) &&
                          (blockIdx.y >= 1) && (blockIdx.y <= 14);

    float mse_acc = interior ? phaseA<false>(xp, yp, row0, col0, tid, H, G2)
                             : phaseA<true >(xp, yp, row0, col0, tid, H, G2);

    __syncthreads();

    // ---------------- Phase B: vertical pass + SSIM epilogue ----------------
    const int col   = tid & 63;
    const int strip = tid >> 6;
    const int rb    = strip * 8;

    u64 wsd[11], wqp[11];
#pragma unroll
    for (int k = 0; k < 10; k++) {
        const ulonglong2 v = *reinterpret_cast<const ulonglong2*>(&H[rb + k][col]);
        wsd[k] = v.x; wqp[k] = v.y;
    }

    float ssim_acc = 0.f;
#pragma unroll
    for (int r = 0; r < 8; r++) {
        const ulonglong2 v = *reinterpret_cast<const ulonglong2*>(&H[rb + r + 10][col]);
        wsd[(r + 10) % 11] = v.x; wqp[(r + 10) % 11] = v.y;

        u64 sd = f2mul(G2[5], wsd[(r + 5) % 11]);
        u64 qp = f2mul(G2[5], wqp[(r + 5) % 11]);
#pragma unroll
        for (int k = 0; k < 5; k++) {
            sd = f2fma(G2[k], f2add(wsd[(r + k) % 11], wsd[(r + 10 - k) % 11]), sd);
            qp = f2fma(G2[k], f2add(wqp[(r + k) % 11], wqp[(r + 10 - k) % 11]), qp);
        }
        float S, D, Q, P;
        upk(sd, S, D); upk(qp, Q, P);
        const float S2  = S * S;
        const float D2  = D * D;
        const float A   = 0.5f * (S2 - D2);   // 2*mu1*mu2
        const float Msq = 0.5f * (S2 + D2);   // mu1^2 + mu2^2
        const float num = (A + C1F) * (fmaf(2.f, P, -A) + C2F);
        const float den = (Msq + C1F) * ((Q - Msq) + C2F);
        ssim_acc += __fdividef(num, den);
    }

    // ---------------- Reduction ----------------
#pragma unroll
    for (int o = 16; o > 0; o >>= 1) {
        mse_acc  += __shfl_down_sync(0xffffffffu, mse_acc,  o);
        ssim_acc += __shfl_down_sync(0xffffffffu, ssim_acc, o);
    }
    const int wid = tid >> 5;
    if ((tid & 31) == 0) { red_m[wid] = mse_acc; red_s[wid] = ssim_acc; }
    __syncthreads();
    if (tid < 32) {
        float m  = (tid < 8) ? red_m[tid] : 0.f;
        float ss = (tid < 8) ? red_s[tid] : 0.f;
#pragma unroll
        for (int o = 4; o > 0; o >>= 1) {
            m  += __shfl_down_sync(0xffffffffu, m,  o);
            ss += __shfl_down_sync(0xffffffffu, ss, o);
        }
        if (tid == 0) {
            atomicAdd(&g_acc[0], (double)m);
            atomicAdd(&g_acc[1], (double)ss);
        }
    }
}

__global__ void finalize_kernel(float* out) {
    const double mse  = g_acc[0] / NPIX;
    const double ssim = g_acc[1] / NPIX;
    out[0] = (float)(0.7 * mse + 0.3 * (1.0 - ssim));
}

extern "C" void kernel_launch(void* const* d_in, const int* in_sizes, int n_in,
                              void* d_out, int out_size)
{
    const float* recon = (const float*)d_in[0];
    const float* orig  = (const float*)d_in[1];
    float* out = (float*)d_out;

    init_acc_kernel<<<1, 1>>>();
    dim3 grid(IMG / TW, IMG / TH, NPLANES);   // 8 x 16 x 192
    ssim_mse_kernel<<<grid, NT>>>(recon, orig);
    finalize_kernel<<<1, 1>>>(out);
}

// round 3
// speedup vs baseline: 1.1714x; 1.1138x over previous
#include <cuda_runtime.h>

#define IMG      512
#define TW       64
#define TH       32
#define HROWS    42
#define HSTRIDE  65
#define NT       256
#define NPLANES  192
#define NBLOCKS  (8 * 16 * 192)
#define NPIX     (64.0 * 3.0 * 512.0 * 512.0)

typedef unsigned long long u64;

__device__ constexpr float GW[6] = {
    1.0283886e-3f, 7.5988485e-3f, 3.6000773e-2f, 1.0936073e-1f, 2.1300553e-1f,
    2.6601180e-1f
};

#define C1F 4.0e-4f
#define C2F 3.6e-3f

__device__ double g_acc[2];        // [0]=sum (x-y)^2, [1]=sum ssim_map
__device__ unsigned int g_count;   // zero-initialized; reset by last block

// ---------- packed f32x2 helpers ----------
__device__ __forceinline__ u64 pk2(float lo, float hi) {
    u64 r; asm("mov.b64 %0,{%1,%2};" : "=l"(r) : "f"(lo), "f"(hi)); return r;
}
__device__ __forceinline__ void upk(u64 a, float& lo, float& hi) {
    asm("mov.b64 {%0,%1},%2;" : "=f"(lo), "=f"(hi) : "l"(a));
}
__device__ __forceinline__ u64 f2fma(u64 a, u64 b, u64 c) {
    u64 d; asm("fma.rn.f32x2 %0,%1,%2,%3;" : "=l"(d) : "l"(a), "l"(b), "l"(c)); return d;
}
__device__ __forceinline__ u64 f2add(u64 a, u64 b) {
    u64 d; asm("add.rn.f32x2 %0,%1,%2;" : "=l"(d) : "l"(a), "l"(b)); return d;
}
__device__ __forceinline__ u64 f2mul(u64 a, u64 b) {
    u64 d; asm("mul.rn.f32x2 %0,%1,%2;" : "=l"(d) : "l"(a), "l"(b)); return d;
}

// 11-tap symmetric conv on packed pairs: 5 add2 + 1 mul2 + 5 fma2
__device__ __forceinline__ u64 conv11(const u64* w, const u64* G2) {
    u64 acc = f2mul(G2[5], w[5]);
#pragma unroll
    for (int k = 0; k < 5; k++)
        acc = f2fma(G2[k], f2add(w[k], w[10 - k]), acc);
    return acc;
}

// ---------------- Phase A: full slot (H rows 0..31, 8 outputs) ----------------
template <bool SAFE>
__device__ __forceinline__ u64 fullSlot(
    const float* __restrict__ xp, const float* __restrict__ yp,
    int row0, int col0, int tid, float4 (*H)[HSTRIDE], const u64* G2)
{
    const int r = tid >> 3;            // 0..31
    const int g = tid & 7;             // 0..7
    const int rimg = row0 - 5 + r;
    const int cb   = col0 + g * 8 - 8; // 32B-aligned base; window = buf[3..20]

    float xa[24], ya[24];
    if (!SAFE) {
        const float4* xr = reinterpret_cast<const float4*>(xp + (size_t)rimg * IMG + cb);
        const float4* yr = reinterpret_cast<const float4*>(yp + (size_t)rimg * IMG + cb);
#pragma unroll
        for (int v = 0; v < 6; v++) {
            float4 t = __ldg(xr + v);
            xa[4*v] = t.x; xa[4*v+1] = t.y; xa[4*v+2] = t.z; xa[4*v+3] = t.w;
            float4 u = __ldg(yr + v);
            ya[4*v] = u.x; ya[4*v+1] = u.y; ya[4*v+2] = u.z; ya[4*v+3] = u.w;
        }
    } else {
        const bool rok = ((unsigned)rimg < IMG);
        const float* xr = xp + (size_t)rimg * IMG;
        const float* yr = yp + (size_t)rimg * IMG;
#pragma unroll
        for (int i = 0; i < 24; i++) {
            const int c = cb + i;
            const bool ok = rok && ((unsigned)c < IMG);
            xa[i] = ok ? __ldg(xr + c) : 0.f;
            ya[i] = ok ? __ldg(yr + c) : 0.f;
        }
    }

    u64 wsd[18], wqp[18];
#pragma unroll
    for (int i = 0; i < 18; i++) {
        const float xv = xa[i + 3], yv = ya[i + 3];
        wsd[i] = pk2(xv + yv, xv - yv);
        wqp[i] = pk2(fmaf(xv, xv, yv * yv), xv * yv);
    }

    u64 msep = 0;                      // hi lane accumulates D^2
    if (r >= 5) {
#pragma unroll
        for (int i = 5; i < 13; i++) msep = f2fma(wsd[i], wsd[i], msep);
    }

    u64 osd[8], oqp[8];
#pragma unroll
    for (int j = 0; j < 8; j++) osd[j] = conv11(wsd + j, G2);
#pragma unroll
    for (int j = 0; j < 8; j++) oqp[j] = conv11(wqp + j, G2);
#pragma unroll
    for (int j = 0; j < 8; j++) {
        const int jj = (j + g) & 7;    // bank rotation
        float a, b, c, d;
        upk(osd[jj], a, b); upk(oqp[jj], c, d);
        H[r][g * 8 + jj] = make_float4(a, b, c, d);
    }
    return msep;
}

// ---------------- Phase A: quarter slot (H rows 32..41, 4 outputs) ----------------
template <bool SAFE>
__device__ __forceinline__ u64 quarterSlot(
    const float* __restrict__ xp, const float* __restrict__ yp,
    int row0, int col0, int tid, float4 (*H)[HSTRIDE], const u64* G2)
{
    const int r = 32 + (tid >> 4);     // 32..41
    const int q = tid & 15;            // 0..15
    const int rimg = row0 - 5 + r;     // row0+27 .. row0+36
    const int cb   = col0 + q * 4 - 8; // 16B-aligned; window = buf[3..16]

    float xa[20], ya[20];
    if (!SAFE) {
        const float4* xr = reinterpret_cast<const float4*>(xp + (size_t)rimg * IMG + cb);
        const float4* yr = reinterpret_cast<const float4*>(yp + (size_t)rimg * IMG + cb);
#pragma unroll
        for (int v = 0; v < 5; v++) {
            float4 t = __ldg(xr + v);
            xa[4*v] = t.x; xa[4*v+1] = t.y; xa[4*v+2] = t.z; xa[4*v+3] = t.w;
            float4 u = __ldg(yr + v);
            ya[4*v] = u.x; ya[4*v+1] = u.y; ya[4*v+2] = u.z; ya[4*v+3] = u.w;
        }
    } else {
        const bool rok = ((unsigned)rimg < IMG);
        const float* xr = xp + (size_t)rimg * IMG;
        const float* yr = yp + (size_t)rimg * IMG;
#pragma unroll
        for (int i = 0; i < 20; i++) {
            const int c = cb + i;
            const bool ok = rok && ((unsigned)c < IMG);
            xa[i] = ok ? __ldg(xr + c) : 0.f;
            ya[i] = ok ? __ldg(yr + c) : 0.f;
        }
    }

    u64 wsd[14], wqp[14];
#pragma unroll
    for (int i = 0; i < 14; i++) {
        const float xv = xa[i + 3], yv = ya[i + 3];
        wsd[i] = pk2(xv + yv, xv - yv);
        wqp[i] = pk2(fmaf(xv, xv, yv * yv), xv * yv);
    }

    u64 msep = 0;
    if (r < 37) {                      // owned image rows row0+27 .. row0+31
#pragma unroll
        for (int i = 5; i < 9; i++) msep = f2fma(wsd[i], wsd[i], msep);
    }

    u64 osd[4], oqp[4];
#pragma unroll
    for (int j = 0; j < 4; j++) osd[j] = conv11(wsd + j, G2);
#pragma unroll
    for (int j = 0; j < 4; j++) oqp[j] = conv11(wqp + j, G2);
#pragma unroll
    for (int j = 0; j < 4; j++) {
        const int jj = (j + q) & 3;
        float a, b, c, d;
        upk(osd[jj], a, b); upk(oqp[jj], c, d);
        H[r][q * 4 + jj] = make_float4(a, b, c, d);
    }
    return msep;
}

__global__ void __launch_bounds__(NT, 2) ssim_mse_kernel(
    const float* __restrict__ x, const float* __restrict__ y,
    float* __restrict__ out)
{
    __shared__ float4 H[HROWS][HSTRIDE];
    __shared__ float red_m[8], red_s[8];

    const int plane = blockIdx.z;
    const int row0  = blockIdx.y * TH;
    const int col0  = blockIdx.x * TW;
    const float* xp = x + (size_t)plane * (IMG * IMG);
    const float* yp = y + (size_t)plane * (IMG * IMG);
    const int tid = threadIdx.x;

    const u64 G2[6] = { pk2(GW[0], GW[0]), pk2(GW[1], GW[1]), pk2(GW[2], GW[2]),
                        pk2(GW[3], GW[3]), pk2(GW[4], GW[4]), pk2(GW[5], GW[5]) };

    const bool interior = (blockIdx.x >= 1) && (blockIdx.x <= 6) &&
                          (blockIdx.y >= 1) && (blockIdx.y <= 14);

    // ---------------- Phase A ----------------
    u64 msep;
    if (interior) {
        msep = fullSlot<false>(xp, yp, row0, col0, tid, H, G2);
        if (tid < 160) {
            u64 m2 = quarterSlot<false>(xp, yp, row0, col0, tid, H, G2);
            msep = f2add(msep, m2);
        }
    } else {
        msep = fullSlot<true>(xp, yp, row0, col0, tid, H, G2);
        if (tid < 160) {
            u64 m2 = quarterSlot<true>(xp, yp, row0, col0, tid, H, G2);
            msep = f2add(msep, m2);
        }
    }
    float mse_lo, mse_acc;
    upk(msep, mse_lo, mse_acc);        // hi lane = sum of D^2

    __syncthreads();

    // ---------------- Phase B: vertical pass + SSIM epilogue ----------------
    const int col   = tid & 63;
    const int strip = tid >> 6;
    const int rb    = strip * 8;

    u64 wsd[11], wqp[11];
#pragma unroll
    for (int k = 0; k < 10; k++) {
        const ulonglong2 v = *reinterpret_cast<const ulonglong2*>(&H[rb + k][col]);
        wsd[k] = v.x; wqp[k] = v.y;
    }

    float ssim_acc = 0.f;
#pragma unroll
    for (int r = 0; r < 8; r++) {
        const ulonglong2 v = *reinterpret_cast<const ulonglong2*>(&H[rb + r + 10][col]);
        wsd[(r + 10) % 11] = v.x; wqp[(r + 10) % 11] = v.y;

        u64 sd = f2mul(G2[5], wsd[(r + 5) % 11]);
        u64 qp = f2mul(G2[5], wqp[(r + 5) % 11]);
#pragma unroll
        for (int k = 0; k < 5; k++) {
            sd = f2fma(G2[k], f2add(wsd[(r + k) % 11], wsd[(r + 10 - k) % 11]), sd);
            qp = f2fma(G2[k], f2add(wqp[(r + k) % 11], wqp[(r + 10 - k) % 11]), qp);
        }
        float S, D, Q, P;
        upk(sd, S, D); upk(qp, Q, P);
        const float S2  = S * S;
        const float D2  = D * D;
        const float A   = 0.5f * (S2 - D2);   // 2*mu1*mu2
        const float Msq = 0.5f * (S2 + D2);   // mu1^2 + mu2^2
        const float num = (A + C1F) * (fmaf(2.f, P, -A) + C2F);
        const float den = (Msq + C1F) * ((Q - Msq) + C2F);
        ssim_acc += __fdividef(num, den);
    }

    // ---------------- Reduction + fused finalize ----------------
#pragma unroll
    for (int o = 16; o > 0; o >>= 1) {
        mse_acc  += __shfl_down_sync(0xffffffffu, mse_acc,  o);
        ssim_acc += __shfl_down_sync(0xffffffffu, ssim_acc, o);
    }
    const int wid = tid >> 5;
    if ((tid & 31) == 0) { red_m[wid] = mse_acc; red_s[wid] = ssim_acc; }
    __syncthreads();
    if (tid < 32) {
        float m  = (tid < 8) ? red_m[tid] : 0.f;
        float ss = (tid < 8) ? red_s[tid] : 0.f;
#pragma unroll
        for (int o = 4; o > 0; o >>= 1) {
            m  += __shfl_down_sync(0xffffffffu, m,  o);
            ss += __shfl_down_sync(0xffffffffu, ss, o);
        }
        if (tid == 0) {
            atomicAdd(&g_acc[0], (double)m);
            atomicAdd(&g_acc[1], (double)ss);
            __threadfence();
            const unsigned c = atomicAdd(&g_count, 1u);
            if (c == NBLOCKS - 1) {            // last block: finalize + reset
                __threadfence();
                const double mse  = g_acc[0] / NPIX;
                const double ssim = g_acc[1] / NPIX;
                out[0] = (float)(0.7 * mse + 0.3 * (1.0 - ssim));
                g_acc[0] = 0.0;
                g_acc[1] = 0.0;
                __threadfence();
                g_count = 0u;
            }
        }
    }
}

extern "C" void kernel_launch(void* const* d_in, const int* in_sizes, int n_in,
                              void* d_out, int out_size)
{
    const float* recon = (const float*)d_in[0];
    const float* orig  = (const float*)d_in[1];
    float* out = (float*)d_out;

    dim3 grid(IMG / TW, IMG / TH, NPLANES);   // 8 x 16 x 192 = 24576 blocks
    ssim_mse_kernel<<<grid, NT>>>(recon, orig, out);
}

// round 5
// speedup vs baseline: 1.7631x; 1.5052x over previous
#include <cuda_runtime.h>

#define IMG      512
#define TW       64
#define TH       32
#define HROWS    42
#define HSTRIDE  66          // even -> 528B row stride, 16B-aligned float4 stores
#define NT       256
#define NPLANES  192
#define NBLOCKS  (8 * 16 * 192)
#define NPIX     (64.0 * 3.0 * 512.0 * 512.0)

typedef unsigned long long u64;

__device__ constexpr float GW[6] = {
    1.0283886e-3f, 7.5988485e-3f, 3.6000773e-2f, 1.0936073e-1f, 2.1300553e-1f,
    2.6601180e-1f
};

#define C1F 4.0e-4f
#define C2F 3.6e-3f

__device__ double g_acc[2];
__device__ unsigned int g_count;

// ---------- packed f32x2 helpers ----------
__device__ __forceinline__ u64 pk2(float lo, float hi) {
    u64 r; asm("mov.b64 %0,{%1,%2};" : "=l"(r) : "f"(lo), "f"(hi)); return r;
}
__device__ __forceinline__ void upk(u64 a, float& lo, float& hi) {
    asm("mov.b64 {%0,%1},%2;" : "=f"(lo), "=f"(hi) : "l"(a));
}
__device__ __forceinline__ u64 f2fma(u64 a, u64 b, u64 c) {
    u64 d; asm("fma.rn.f32x2 %0,%1,%2,%3;" : "=l"(d) : "l"(a), "l"(b), "l"(c)); return d;
}
__device__ __forceinline__ u64 f2add(u64 a, u64 b) {
    u64 d; asm("add.rn.f32x2 %0,%1,%2;" : "=l"(d) : "l"(a), "l"(b)); return d;
}
__device__ __forceinline__ u64 f2mul(u64 a, u64 b) {
    u64 d; asm("mul.rn.f32x2 %0,%1,%2;" : "=l"(d) : "l"(a), "l"(b)); return d;
}

// 11-tap symmetric conv on packed pairs
__device__ __forceinline__ u64 conv11(const u64* w, const u64* G2) {
    u64 acc = f2mul(G2[5], w[5]);
#pragma unroll
    for (int k = 0; k < 5; k++)
        acc = f2fma(G2[k], f2add(w[k], w[10 - k]), acc);
    return acc;
}

// ---------------- Phase A: uniform 4-output slots ----------------
// MODE 0: fully interior. MODE 1: row-guard only. MODE 2: row+col guards.
template <int MODE>
__device__ __forceinline__ u64 phaseA(
    const float* __restrict__ xp, const float* __restrict__ yp,
    int row0, int col0, int tid,
    u64 (*Hsd)[HSTRIDE], u64 (*Hqp)[HSTRIDE], const u64* G2)
{
    u64 msep = 0;
#pragma unroll
    for (int kk = 0; kk < 3; kk++) {
        const int s = tid + kk * NT;
        if (kk == 2 && s >= 672) break;
        const int r = s >> 4;          // 0..41
        const int q = s & 15;          // 0..15
        const int rimg = row0 - 5 + r;
        const int cb   = col0 + q * 4 - 8;   // 16B aligned

        u64 wsd[14], wqp[14];
        bool vec;
        if (MODE == 0) vec = true;
        else {
            const bool rok = ((unsigned)rimg < IMG);
            if (MODE == 1) vec = rok;
            else vec = rok && (cb >= 0) && (cb + 20 <= IMG);
            if (!vec && (MODE == 2) && rok) {
                // scalar guarded: window cols cb+3 .. cb+16
#pragma unroll
                for (int m = 0; m < 14; m++) {
                    const int c = cb + 3 + m;
                    float xv = 0.f, yv = 0.f;
                    if ((unsigned)c < IMG) {
                        xv = __ldg(xp + (size_t)rimg * IMG + c);
                        yv = __ldg(yp + (size_t)rimg * IMG + c);
                    }
                    wsd[m] = pk2(xv + yv, xv - yv);
                    wqp[m] = pk2(fmaf(xv, xv, yv * yv), xv * yv);
                }
                goto havewin;
            }
            if (!vec) {                // out-of-image row: all zeros
#pragma unroll
                for (int m = 0; m < 14; m++) { wsd[m] = 0; wqp[m] = 0; }
                goto havewin;
            }
        }
        {
            const float4* xr = reinterpret_cast<const float4*>(xp + (size_t)rimg * IMG + cb);
            const float4* yr = reinterpret_cast<const float4*>(yp + (size_t)rimg * IMG + cb);
#pragma unroll
            for (int v = 0; v < 5; v++) {
                const float4 fx = __ldg(xr + v);
                const float4 fy = __ldg(yr + v);
                const float xe[4] = { fx.x, fx.y, fx.z, fx.w };
                const float ye[4] = { fy.x, fy.y, fy.z, fy.w };
#pragma unroll
                for (int e = 0; e < 4; e++) {
                    const int i = 4 * v + e;       // col cb+i; window is i in [3,17)
                    if (i >= 3 && i < 17) {
                        const float xv = xe[e], yv = ye[e];
                        wsd[i - 3] = pk2(xv + yv, xv - yv);
                        wqp[i - 3] = pk2(fmaf(xv, xv, yv * yv), xv * yv);
                    }
                }
            }
        }
    havewin:
        // MSE: owned rows r in [5,37), owned cols -> wsd[5..8] (hi lane = D)
        if (r >= 5 && r < 37) {
#pragma unroll
            for (int m = 5; m < 9; m++) msep = f2fma(wsd[m], wsd[m], msep);
        }

        u64 osd[4], oqp[4];
#pragma unroll
        for (int j = 0; j < 4; j++) osd[j] = conv11(wsd + j, G2);
#pragma unroll
        for (int j = 0; j < 4; j++) oqp[j] = conv11(wqp + j, G2);

        {
            float a0, b0, a1, b1;
            float4* p = reinterpret_cast<float4*>(&Hsd[r][q * 4]);
            upk(osd[0], a0, b0); upk(osd[1], a1, b1);
            p[0] = make_float4(a0, b0, a1, b1);
            upk(osd[2], a0, b0); upk(osd[3], a1, b1);
            p[1] = make_float4(a0, b0, a1, b1);
            float4* p2 = reinterpret_cast<float4*>(&Hqp[r][q * 4]);
            upk(oqp[0], a0, b0); upk(oqp[1], a1, b1);
            p2[0] = make_float4(a0, b0, a1, b1);
            upk(oqp[2], a0, b0); upk(oqp[3], a1, b1);
            p2[1] = make_float4(a0, b0, a1, b1);
        }
    }
    return msep;
}

__global__ void __launch_bounds__(NT, 3) ssim_mse_kernel(
    const float* __restrict__ x, const float* __restrict__ y,
    float* __restrict__ out)
{
    __shared__ alignas(16) u64 Hsd[HROWS][HSTRIDE];
    __shared__ alignas(16) u64 Hqp[HROWS][HSTRIDE];
    __shared__ float red_m[8], red_s[8];

    const int plane = blockIdx.z;
    const int row0  = blockIdx.y * TH;
    const int col0  = blockIdx.x * TW;
    const float* xp = x + (size_t)plane * (IMG * IMG);
    const float* yp = y + (size_t)plane * (IMG * IMG);
    const int tid = threadIdx.x;

    const u64 G2[6] = { pk2(GW[0], GW[0]), pk2(GW[1], GW[1]), pk2(GW[2], GW[2]),
                        pk2(GW[3], GW[3]), pk2(GW[4], GW[4]), pk2(GW[5], GW[5]) };

    const bool xin = (blockIdx.x >= 1) && (blockIdx.x <= 6);
    const bool yin = (blockIdx.y >= 1) && (blockIdx.y <= 14);

    u64 msep;
    if (xin && yin) msep = phaseA<0>(xp, yp, row0, col0, tid, Hsd, Hqp, G2);
    else if (xin)   msep = phaseA<1>(xp, yp, row0, col0, tid, Hsd, Hqp, G2);
    else            msep = phaseA<2>(xp, yp, row0, col0, tid, Hsd, Hqp, G2);

    float mse_lo, mse_acc;
    upk(msep, mse_lo, mse_acc);        // hi lane = sum D^2

    __syncthreads();

    // ---------------- Phase B: two-pass vertical conv ----------------
    const int col   = tid & 63;
    const int strip = tid >> 6;
    const int rb    = strip * 8;

    u64 ring[11];
    u64 vsd[8];

    // pass 1: SD stream
#pragma unroll
    for (int k = 0; k < 10; k++) ring[k] = Hsd[rb + k][col];
#pragma unroll
    for (int r = 0; r < 8; r++) {
        ring[(r + 10) % 11] = Hsd[rb + r + 10][col];
        u64 acc = f2mul(G2[5], ring[(r + 5) % 11]);
#pragma unroll
        for (int k = 0; k < 5; k++)
            acc = f2fma(G2[k], f2add(ring[(r + k) % 11], ring[(r + 10 - k) % 11]), acc);
        vsd[r] = acc;
    }

    // pass 2: QP stream + epilogue
    float ssim_acc = 0.f;
#pragma unroll
    for (int k = 0; k < 10; k++) ring[k] = Hqp[rb + k][col];
#pragma unroll
    for (int r = 0; r < 8; r++) {
        ring[(r + 10) % 11] = Hqp[rb + r + 10][col];
        u64 acc = f2mul(G2[5], ring[(r + 5) % 11]);
#pragma unroll
        for (int k = 0; k < 5; k++)
            acc = f2fma(G2[k], f2add(ring[(r + k) % 11], ring[(r + 10 - k) % 11]), acc);

        float S, D, Q, P;
        upk(vsd[r], S, D); upk(acc, Q, P);
        const float S2  = S * S;
        const float D2  = D * D;
        const float A   = 0.5f * (S2 - D2);   // 2*mu1*mu2
        const float Msq = 0.5f * (S2 + D2);   // mu1^2 + mu2^2
        const float num = (A + C1F) * (fmaf(2.f, P, -A) + C2F);
        const float den = (Msq + C1F) * ((Q - Msq) + C2F);
        ssim_acc += __fdividef(num, den);
    }

    // ---------------- Reduction + fused finalize ----------------
#pragma unroll
    for (int o = 16; o > 0; o >>= 1) {
        mse_acc  += __shfl_down_sync(0xffffffffu, mse_acc,  o);
        ssim_acc += __shfl_down_sync(0xffffffffu, ssim_acc, o);
    }
    const int wid = tid >> 5;
    if ((tid & 31) == 0) { red_m[wid] = mse_acc; red_s[wid] = ssim_acc; }
    __syncthreads();
    if (tid < 32) {
        float m  = (tid < 8) ? red_m[tid] : 0.f;
        float ss = (tid < 8) ? red_s[tid] : 0.f;
#pragma unroll
        for (int o = 4; o > 0; o >>= 1) {
            m  += __shfl_down_sync(0xffffffffu, m,  o);
            ss += __shfl_down_sync(0xffffffffu, ss, o);
        }
        if (tid == 0) {
            atomicAdd(&g_acc[0], (double)m);
            atomicAdd(&g_acc[1], (double)ss);
            __threadfence();
            const unsigned c = atomicAdd(&g_count, 1u);
            if (c == NBLOCKS - 1) {
                __threadfence();
                const double mse  = g_acc[0] / NPIX;
                const double ssim = g_acc[1] / NPIX;
                out[0] = (float)(0.7 * mse + 0.3 * (1.0 - ssim));
                g_acc[0] = 0.0;
                g_acc[1] = 0.0;
                __threadfence();
                g_count = 0u;
            }
        }
    }
}

extern "C" void kernel_launch(void* const* d_in, const int* in_sizes, int n_in,
                              void* d_out, int out_size)
{
    const float* recon = (const float*)d_in[0];
    const float* orig  = (const float*)d_in[1];
    float* out = (float*)d_out;

    dim3 grid(IMG / TW, IMG / TH, NPLANES);   // 24576 blocks
    ssim_mse_kernel<<<grid, NT>>>(recon, orig, out);
}

// round 6
// speedup vs baseline: 2.0633x; 1.1703x over previous
#include <cuda_runtime.h>

#define IMG      512
#define TW       64
#define TH       32
#define HROWS    42
#define HSTRIDE  66          // 528B row stride, 16B-aligned float4 stores
#define NT       256
#define NPLANES  192
#define NBLOCKS  (8 * 16 * 192)
#define NPIX     (64.0 * 3.0 * 512.0 * 512.0)

typedef unsigned long long u64;

__device__ constexpr float GW[6] = {
    1.0283886e-3f, 7.5988485e-3f, 3.6000773e-2f, 1.0936073e-1f, 2.1300553e-1f,
    2.6601180e-1f
};

#define C1F 4.0e-4f
#define C2F 3.6e-3f

__device__ double g_acc[2];
__device__ unsigned int g_count;

// ---------- packed f32x2 helpers ----------
__device__ __forceinline__ u64 pk2(float lo, float hi) {
    u64 r; asm("mov.b64 %0,{%1,%2};" : "=l"(r) : "f"(lo), "f"(hi)); return r;
}
__device__ __forceinline__ void upk(u64 a, float& lo, float& hi) {
    asm("mov.b64 {%0,%1},%2;" : "=f"(lo), "=f"(hi) : "l"(a));
}
__device__ __forceinline__ u64 f2fma(u64 a, u64 b, u64 c) {
    u64 d; asm("fma.rn.f32x2 %0,%1,%2,%3;" : "=l"(d) : "l"(a), "l"(b), "l"(c)); return d;
}
__device__ __forceinline__ u64 f2add(u64 a, u64 b) {
    u64 d; asm("add.rn.f32x2 %0,%1,%2;" : "=l"(d) : "l"(a), "l"(b)); return d;
}
__device__ __forceinline__ u64 f2mul(u64 a, u64 b) {
    u64 d; asm("mul.rn.f32x2 %0,%1,%2;" : "=l"(d) : "l"(a), "l"(b)); return d;
}

// 11-tap symmetric conv on packed pairs
__device__ __forceinline__ u64 conv11(const u64* w, const u64* G2) {
    u64 acc = f2mul(G2[5], w[5]);
#pragma unroll
    for (int k = 0; k < 5; k++)
        acc = f2fma(G2[k], f2add(w[k], w[10 - k]), acc);
    return acc;
}

// ---------------- Phase A: uniform 4-output slots ----------------
// Streams: SD = (x+y, x-y); UV = ((x+y)^2, (x-y)^2) derived in place.
// MODE 0: interior. MODE 1: row-guard only. MODE 2: row+col guards.
template <int MODE>
__device__ __forceinline__ u64 phaseA(
    const float* __restrict__ xp, const float* __restrict__ yp,
    int row0, int col0, int tid,
    u64 (*Hsd)[HSTRIDE], u64 (*Huv)[HSTRIDE], const u64* G2)
{
    u64 msep = 0;
#pragma unroll
    for (int kk = 0; kk < 3; kk++) {
        const int s = tid + kk * NT;
        if (kk == 2 && s >= 672) break;
        const int r = s >> 4;          // 0..41
        const int q = s & 15;          // 0..15
        const int rimg = row0 - 5 + r;
        const int cb   = col0 + q * 4 - 8;   // 16B aligned

        u64 wsd[14];
        bool vec;
        if (MODE == 0) vec = true;
        else {
            const bool rok = ((unsigned)rimg < IMG);
            if (MODE == 1) vec = rok;
            else vec = rok && (cb >= 0) && (cb + 20 <= IMG);
            if (!vec && (MODE == 2) && rok) {
#pragma unroll
                for (int m = 0; m < 14; m++) {
                    const int c = cb + 3 + m;
                    float xv = 0.f, yv = 0.f;
                    if ((unsigned)c < IMG) {
                        xv = __ldg(xp + (size_t)rimg * IMG + c);
                        yv = __ldg(yp + (size_t)rimg * IMG + c);
                    }
                    wsd[m] = pk2(xv + yv, xv - yv);
                }
                goto havewin;
            }
            if (!vec) {
#pragma unroll
                for (int m = 0; m < 14; m++) wsd[m] = 0;
                goto havewin;
            }
        }
        {
            const float4* xr = reinterpret_cast<const float4*>(xp + (size_t)rimg * IMG + cb);
            const float4* yr = reinterpret_cast<const float4*>(yp + (size_t)rimg * IMG + cb);
#pragma unroll
            for (int v = 0; v < 5; v++) {
                const float4 fx = __ldg(xr + v);
                const float4 fy = __ldg(yr + v);
                const float xe[4] = { fx.x, fx.y, fx.z, fx.w };
                const float ye[4] = { fy.x, fy.y, fy.z, fy.w };
#pragma unroll
                for (int e = 0; e < 4; e++) {
                    const int i = 4 * v + e;       // col cb+i; window i in [3,17)
                    if (i >= 3 && i < 17)
                        wsd[i - 3] = pk2(xe[e] + ye[e], xe[e] - ye[e]);
                }
            }
        }
    havewin:
        // MSE: owned rows r in [5,37); hi lane of wsd = D
        if (r >= 5 && r < 37) {
#pragma unroll
            for (int m = 5; m < 9; m++) msep = f2fma(wsd[m], wsd[m], msep);
        }

        // SD conv + store
        {
            u64 o0 = conv11(wsd + 0, G2), o1 = conv11(wsd + 1, G2);
            u64 o2 = conv11(wsd + 2, G2), o3 = conv11(wsd + 3, G2);
            float a0, b0, a1, b1;
            float4* p = reinterpret_cast<float4*>(&Hsd[r][q * 4]);
            upk(o0, a0, b0); upk(o1, a1, b1);
            p[0] = make_float4(a0, b0, a1, b1);
            upk(o2, a0, b0); upk(o3, a1, b1);
            p[1] = make_float4(a0, b0, a1, b1);
        }

        // transform window in place: (s,d) -> (s^2, d^2), then UV conv + store
#pragma unroll
        for (int m = 0; m < 14; m++) wsd[m] = f2mul(wsd[m], wsd[m]);
        {
            u64 o0 = conv11(wsd + 0, G2), o1 = conv11(wsd + 1, G2);
            u64 o2 = conv11(wsd + 2, G2), o3 = conv11(wsd + 3, G2);
            float a0, b0, a1, b1;
            float4* p = reinterpret_cast<float4*>(&Huv[r][q * 4]);
            upk(o0, a0, b0); upk(o1, a1, b1);
            p[0] = make_float4(a0, b0, a1, b1);
            upk(o2, a0, b0); upk(o3, a1, b1);
            p[1] = make_float4(a0, b0, a1, b1);
        }
    }
    return msep;
}

__global__ void __launch_bounds__(NT, 4) ssim_mse_kernel(
    const float* __restrict__ x, const float* __restrict__ y,
    float* __restrict__ out)
{
    __shared__ alignas(16) u64 Hsd[HROWS][HSTRIDE];
    __shared__ alignas(16) u64 Huv[HROWS][HSTRIDE];
    __shared__ float red_m[8], red_s[8];

    const int plane = blockIdx.z;
    const int row0  = blockIdx.y * TH;
    const int col0  = blockIdx.x * TW;
    const float* xp = x + (size_t)plane * (IMG * IMG);
    const float* yp = y + (size_t)plane * (IMG * IMG);
    const int tid = threadIdx.x;

    const u64 G2[6] = { pk2(GW[0], GW[0]), pk2(GW[1], GW[1]), pk2(GW[2], GW[2]),
                        pk2(GW[3], GW[3]), pk2(GW[4], GW[4]), pk2(GW[5], GW[5]) };

    const bool xin = (blockIdx.x >= 1) && (blockIdx.x <= 6);
    const bool yin = (blockIdx.y >= 1) && (blockIdx.y <= 14);

    u64 msep;
    if (xin && yin) msep = phaseA<0>(xp, yp, row0, col0, tid, Hsd, Huv, G2);
    else if (xin)   msep = phaseA<1>(xp, yp, row0, col0, tid, Hsd, Huv, G2);
    else            msep = phaseA<2>(xp, yp, row0, col0, tid, Hsd, Huv, G2);

    float mse_lo, mse_acc;
    upk(msep, mse_lo, mse_acc);        // hi lane = sum D^2

    __syncthreads();

    // ---------------- Phase B: two-pass vertical conv ----------------
    const int col   = tid & 63;
    const int strip = tid >> 6;
    const int rb    = strip * 8;

    u64 ring[11];
    u64 vsd[8];

    // pass 1: SD stream
#pragma unroll
    for (int k = 0; k < 10; k++) ring[k] = Hsd[rb + k][col];
#pragma unroll
    for (int r = 0; r < 8; r++) {
        ring[(r + 10) % 11] = Hsd[rb + r + 10][col];
        u64 acc = f2mul(G2[5], ring[(r + 5) % 11]);
#pragma unroll
        for (int k = 0; k < 5; k++)
            acc = f2fma(G2[k], f2add(ring[(r + k) % 11], ring[(r + 10 - k) % 11]), acc);
        vsd[r] = acc;
    }

    // pass 2: UV stream + epilogue
    float ssim_acc = 0.f;
#pragma unroll
    for (int k = 0; k < 10; k++) ring[k] = Huv[rb + k][col];
#pragma unroll
    for (int r = 0; r < 8; r++) {
        ring[(r + 10) % 11] = Huv[rb + r + 10][col];
        u64 acc = f2mul(G2[5], ring[(r + 5) % 11]);
#pragma unroll
        for (int k = 0; k < 5; k++)
            acc = f2fma(G2[k], f2add(ring[(r + k) % 11], ring[(r + 10 - k) % 11]), acc);

        float U, V, S2, D2;
        upk(acc, U, V);
        upk(f2mul(vsd[r], vsd[r]), S2, D2);
        const float varS = U - S2;           // conv(s^2) - S^2  (s = x+y)
        const float varD = V - D2;           // conv(d^2) - D^2  (d = x-y)
        const float A   = 0.5f * (S2 - D2);  // 2*mu1*mu2
        const float Msq = 0.5f * (S2 + D2);  // mu1^2 + mu2^2
        const float num = (A + C1F) * (0.5f * (varS - varD) + C2F);
        const float den = (Msq + C1F) * (0.5f * (varS + varD) + C2F);
        ssim_acc += __fdividef(num, den);
    }

    // ---------------- Reduction + fused finalize ----------------
#pragma unroll
    for (int o = 16; o > 0; o >>= 1) {
        mse_acc  += __shfl_down_sync(0xffffffffu, mse_acc,  o);
        ssim_acc += __shfl_down_sync(0xffffffffu, ssim_acc, o);
    }
    const int wid = tid >> 5;
    if ((tid & 31) == 0) { red_m[wid] = mse_acc; red_s[wid] = ssim_acc; }
    __syncthreads();
    if (tid < 32) {
        float m  = (tid < 8) ? red_m[tid] : 0.f;
        float ss = (tid < 8) ? red_s[tid] : 0.f;
#pragma unroll
        for (int o = 4; o > 0; o >>= 1) {
            m  += __shfl_down_sync(0xffffffffu, m,  o);
            ss += __shfl_down_sync(0xffffffffu, ss, o);
        }
        if (tid == 0) {
            atomicAdd(&g_acc[0], (double)m);
            atomicAdd(&g_acc[1], (double)ss);
            __threadfence();
            const unsigned c = atomicAdd(&g_count, 1u);
            if (c == NBLOCKS - 1) {
                __threadfence();
                const double mse  = g_acc[0] / NPIX;
                const double ssim = g_acc[1] / NPIX;
                out[0] = (float)(0.7 * mse + 0.3 * (1.0 - ssim));
                g_acc[0] = 0.0;
                g_acc[1] = 0.0;
                __threadfence();
                g_count = 0u;
            }
        }
    }
}

extern "C" void kernel_launch(void* const* d_in, const int* in_sizes, int n_in,
                              void* d_out, int out_size)
{
    const float* recon = (const float*)d_in[0];
    const float* orig  = (const float*)d_in[1];
    float* out = (float*)d_out;

    dim3 grid(IMG / TW, IMG / TH, NPLANES);   // 24576 blocks
    ssim_mse_kernel<<<grid, NT>>>(recon, orig, out);
}